// round 1
// baseline (speedup 1.0000x reference)
#include <cuda_runtime.h>
#include <cstdint>

// ---------------------------------------------------------------------------
// FMoELinearProj: out[t,s] = sum_d ( sum_i x[t,i]*W[e,o=d,i] + b[e,d] ) * C[e,s,d]
// Tokens are contiguous per expert; counts sum to T. Two grouped GEMMs with a
// device-resident intermediate y[T, D_out].
// ---------------------------------------------------------------------------

#define TM 128
#define TN 128
#define BK 8
#define NTHREADS 256

// Static scratch (allocation inside kernel_launch is forbidden).
__device__ int   g_off[64 + 1];
__device__ int2  g_tiles[1024];
__device__ int   g_ntiles;
__device__ float g_y[8192ull * 4096ull];   // [T, D_out] fp32 (128 MB)

typedef unsigned long long u64;

__device__ __forceinline__ u64 fma2(u64 a, u64 b, u64 c) {
    u64 d;
    asm("fma.rn.f32x2 %0, %1, %2, %3;" : "=l"(d) : "l"(a), "l"(b), "l"(c));
    return d;
}
__device__ __forceinline__ u64 dup2(float x) {
    u64 d;
    asm("mov.b64 %0, {%1, %1};" : "=l"(d) : "f"(x));
    return d;
}

// Build per-expert offsets + (expert, m_base) tile worklist from device counts.
__global__ void setup_kernel(const int* __restrict__ counts, int E) {
    if (threadIdx.x == 0 && blockIdx.x == 0) {
        int off = 0, nt = 0;
        for (int e = 0; e < E; ++e) {
            g_off[e] = off;
            int c = counts[e];
            for (int m = 0; m < c; m += TM) {
                g_tiles[nt].x = e;
                g_tiles[nt].y = m;
                ++nt;
            }
            off += c;
        }
        g_off[E] = off;
        g_ntiles = nt;
    }
}

// Generic grouped GEMM: C[row, n] = sum_k A[row, k] * B[e, n, k] (+ bias[e, n])
// A rows are global token rows (row0 = g_off[e] + m_base).
// YMODE: 0 = use A/C args, 1 = C is g_y, 2 = A is g_y.
template <bool ADD_BIAS, int YMODE>
__global__ __launch_bounds__(NTHREADS, 2)
void moe_gemm(const float* __restrict__ A,
              const float* __restrict__ Bm,
              const float* __restrict__ bias,
              float* __restrict__ C,
              int K, int N)
{
    const int tile_id = blockIdx.y;
    if (tile_id >= g_ntiles) return;

    const int e    = g_tiles[tile_id].x;
    const int m0   = g_tiles[tile_id].y;
    const int row0 = g_off[e] + m0;
    int mrows = g_off[e + 1] - g_off[e] - m0;
    if (mrows > TM) mrows = TM;
    const int n0 = blockIdx.x * TN;

    const float* Ap = (YMODE == 2) ? (const float*)g_y : A;
    float*       Cp = (YMODE == 1) ? g_y : C;

    __shared__ __align__(16) float As[2][BK][TM];
    __shared__ __align__(16) float Bs[2][BK][TN];

    const int tid = threadIdx.x;
    const int tx = tid & 15;        // n fragment selector
    const int ty = tid >> 4;        // m fragment selector
    const int lr = tid >> 1;        // 0..127: tile row loaded by this thread
    const int lk = (tid & 1) * 4;   // 0 or 4: k offset loaded by this thread

    const bool a_ok = lr < mrows;
    const float* Aload = Ap + (size_t)(row0 + lr) * K + lk;
    const float* Bload = Bm + (size_t)e * N * K + (size_t)(n0 + lr) * K + lk;

    float4 a4 = a_ok ? *(const float4*)Aload : make_float4(0.f, 0.f, 0.f, 0.f);
    float4 b4 = *(const float4*)Bload;

    u64 acc[8][4];
#pragma unroll
    for (int i = 0; i < 8; ++i)
#pragma unroll
        for (int j = 0; j < 4; ++j) acc[i][j] = 0ull;

    As[0][lk + 0][lr] = a4.x; As[0][lk + 1][lr] = a4.y;
    As[0][lk + 2][lr] = a4.z; As[0][lk + 3][lr] = a4.w;
    Bs[0][lk + 0][lr] = b4.x; Bs[0][lk + 1][lr] = b4.y;
    Bs[0][lk + 2][lr] = b4.z; Bs[0][lk + 3][lr] = b4.w;
    __syncthreads();

    const int nk = K / BK;
    int buf = 0;
    for (int kt = 0; kt < nk; ++kt) {
        // Prefetch next k-tile from global into registers.
        if (kt + 1 < nk) {
            const float* An = Aload + (size_t)(kt + 1) * BK;
            const float* Bn = Bload + (size_t)(kt + 1) * BK;
            a4 = a_ok ? *(const float4*)An : make_float4(0.f, 0.f, 0.f, 0.f);
            b4 = *(const float4*)Bn;
        }
#pragma unroll
        for (int k = 0; k < BK; ++k) {
            union { float4 v; u64 u[2]; float f[4]; } al, ah, bl, bh;
            al.v = *(const float4*)&As[buf][k][ty * 4];
            ah.v = *(const float4*)&As[buf][k][64 + ty * 4];
            bl.v = *(const float4*)&Bs[buf][k][tx * 4];
            bh.v = *(const float4*)&Bs[buf][k][64 + tx * 4];
#pragma unroll
            for (int i = 0; i < 8; ++i) {
                float av = (i < 4) ? al.f[i] : ah.f[i - 4];
                u64 ad = dup2(av);
                acc[i][0] = fma2(ad, bl.u[0], acc[i][0]);
                acc[i][1] = fma2(ad, bl.u[1], acc[i][1]);
                acc[i][2] = fma2(ad, bh.u[0], acc[i][2]);
                acc[i][3] = fma2(ad, bh.u[1], acc[i][3]);
            }
        }
        buf ^= 1;
        if (kt + 1 < nk) {
            As[buf][lk + 0][lr] = a4.x; As[buf][lk + 1][lr] = a4.y;
            As[buf][lk + 2][lr] = a4.z; As[buf][lk + 3][lr] = a4.w;
            Bs[buf][lk + 0][lr] = b4.x; Bs[buf][lk + 1][lr] = b4.y;
            Bs[buf][lk + 2][lr] = b4.z; Bs[buf][lk + 3][lr] = b4.w;
            __syncthreads();
        }
    }

    // Epilogue
    float bvl[4], bvh[4];
    if (ADD_BIAS) {
        const float* bp = bias + (size_t)e * N + n0;
#pragma unroll
        for (int j = 0; j < 4; ++j) {
            bvl[j] = bp[tx * 4 + j];
            bvh[j] = bp[64 + tx * 4 + j];
        }
    }
#pragma unroll
    for (int i = 0; i < 8; ++i) {
        const int m = (i < 4) ? (ty * 4 + i) : (64 + ty * 4 + (i - 4));
        if (m < mrows) {
            float* crow = Cp + (size_t)(row0 + m) * N + n0;
            float2 v0 = *(float2*)&acc[i][0];
            float2 v1 = *(float2*)&acc[i][1];
            float2 v2 = *(float2*)&acc[i][2];
            float2 v3 = *(float2*)&acc[i][3];
            if (ADD_BIAS) {
                v0.x += bvl[0]; v0.y += bvl[1];
                v1.x += bvl[2]; v1.y += bvl[3];
                v2.x += bvh[0]; v2.y += bvh[1];
                v3.x += bvh[2]; v3.y += bvh[3];
            }
            *(float2*)&crow[tx * 4]          = v0;
            *(float2*)&crow[tx * 4 + 2]      = v1;
            *(float2*)&crow[64 + tx * 4]     = v2;
            *(float2*)&crow[64 + tx * 4 + 2] = v3;
        }
    }
}

extern "C" void kernel_launch(void* const* d_in, const int* in_sizes, int n_in,
                              void* d_out, int out_size) {
    const float* inp  = (const float*)d_in[0];   // [B, L, D_in]
    const int*   cnt  = (const int*)  d_in[1];   // [E]
    const float* wgt  = (const float*)d_in[2];   // [E, D_out, D_in]
    const float* bias = (const float*)d_in[3];   // [E, D_out]
    const float* comp = (const float*)d_in[4];   // [E, S, D_out]
    float* out = (float*)d_out;                  // [T, S] fp32

    const int E     = in_sizes[1];
    const int D_out = in_sizes[3] / E;
    const int D_in  = in_sizes[2] / in_sizes[3];          // (E*Do*Di)/(E*Do)
    const int T     = in_sizes[0] / D_in;
    const int S     = in_sizes[4] / in_sizes[3];          // (E*S*Do)/(E*Do)

    const int maxtiles = T / TM + E;  // upper bound on sum_e ceil(count_e/TM)

    setup_kernel<<<1, 1>>>(cnt, E);

    // GEMM1: y[t, o] = x[t, :] . W[e, o, :] + b[e, o]
    moe_gemm<true, 1><<<dim3(D_out / TN, maxtiles), NTHREADS>>>(
        inp, wgt, bias, nullptr, D_in, D_out);

    // GEMM2: out[t, s] = y[t, :] . C[e, s, :]
    moe_gemm<false, 2><<<dim3(S / TN, maxtiles), NTHREADS>>>(
        nullptr, comp, nullptr, out, D_out, S);
}

// round 2
// speedup vs baseline: 1.0045x; 1.0045x over previous
#include <cuda_runtime.h>
#include <cstdint>

// ---------------------------------------------------------------------------
// FMoELinearProj: out[t,s] = sum_d ( sum_i x[t,i]*W[e,o=d,i] + b[e,d] ) * C[e,s,d]
// Tokens are contiguous per expert; counts sum to T. Two grouped GEMMs with a
// device-resident intermediate y[T, D_out].
// ---------------------------------------------------------------------------

#define TM 128
#define TN 128
#define BK 8
#define NTHREADS 256

// Static scratch (allocation inside kernel_launch is forbidden).
__device__ int   g_off[64 + 1];
__device__ int2  g_tiles[1024];
__device__ int   g_ntiles;
__device__ float g_y[8192ull * 4096ull];   // [T, D_out] fp32 (128 MB)

typedef unsigned long long u64;

__device__ __forceinline__ u64 fma2(u64 a, u64 b, u64 c) {
    u64 d;
    asm("fma.rn.f32x2 %0, %1, %2, %3;" : "=l"(d) : "l"(a), "l"(b), "l"(c));
    return d;
}
__device__ __forceinline__ u64 dup2(float x) {
    u64 d;
    asm("mov.b64 %0, {%1, %1};" : "=l"(d) : "f"(x));
    return d;
}

// Build per-expert offsets + (expert, m_base) tile worklist from device counts.
__global__ void setup_kernel(const int* __restrict__ counts, int E) {
    if (threadIdx.x == 0 && blockIdx.x == 0) {
        int off = 0, nt = 0;
        for (int e = 0; e < E; ++e) {
            g_off[e] = off;
            int c = counts[e];
            for (int m = 0; m < c; m += TM) {
                g_tiles[nt].x = e;
                g_tiles[nt].y = m;
                ++nt;
            }
            off += c;
        }
        g_off[E] = off;
        g_ntiles = nt;
    }
}

// Generic grouped GEMM: C[row, n] = sum_k A[row, k] * B[e, n, k] (+ bias[e, n])
// A rows are global token rows (row0 = g_off[e] + m_base).
// YMODE: 0 = use A/C args, 1 = C is g_y, 2 = A is g_y.
template <bool ADD_BIAS, int YMODE>
__global__ __launch_bounds__(NTHREADS, 2)
void moe_gemm(const float* __restrict__ A,
              const float* __restrict__ Bm,
              const float* __restrict__ bias,
              float* __restrict__ C,
              int K, int N)
{
    const int tile_id = blockIdx.y;
    if (tile_id >= g_ntiles) return;

    const int e    = g_tiles[tile_id].x;
    const int m0   = g_tiles[tile_id].y;
    const int row0 = g_off[e] + m0;
    int mrows = g_off[e + 1] - g_off[e] - m0;
    if (mrows > TM) mrows = TM;
    const int n0 = blockIdx.x * TN;

    const float* Ap = (YMODE == 2) ? (const float*)g_y : A;
    float*       Cp = (YMODE == 1) ? g_y : C;

    __shared__ __align__(16) float As[2][BK][TM];
    __shared__ __align__(16) float Bs[2][BK][TN];

    const int tid = threadIdx.x;
    const int tx = tid & 15;        // n fragment selector
    const int ty = tid >> 4;        // m fragment selector
    const int lr = tid >> 1;        // 0..127: tile row loaded by this thread
    const int lk = (tid & 1) * 4;   // 0 or 4: k offset loaded by this thread

    const bool a_ok = lr < mrows;
    const float* Aload = Ap + (size_t)(row0 + lr) * K + lk;
    const float* Bload = Bm + (size_t)e * N * K + (size_t)(n0 + lr) * K + lk;

    float4 a4 = a_ok ? *(const float4*)Aload : make_float4(0.f, 0.f, 0.f, 0.f);
    float4 b4 = *(const float4*)Bload;

    u64 acc[8][4];
#pragma unroll
    for (int i = 0; i < 8; ++i)
#pragma unroll
        for (int j = 0; j < 4; ++j) acc[i][j] = 0ull;

    As[0][lk + 0][lr] = a4.x; As[0][lk + 1][lr] = a4.y;
    As[0][lk + 2][lr] = a4.z; As[0][lk + 3][lr] = a4.w;
    Bs[0][lk + 0][lr] = b4.x; Bs[0][lk + 1][lr] = b4.y;
    Bs[0][lk + 2][lr] = b4.z; Bs[0][lk + 3][lr] = b4.w;
    __syncthreads();

    const int nk = K / BK;
    int buf = 0;
    for (int kt = 0; kt < nk; ++kt) {
        // Prefetch next k-tile from global into registers.
        if (kt + 1 < nk) {
            const float* An = Aload + (size_t)(kt + 1) * BK;
            const float* Bn = Bload + (size_t)(kt + 1) * BK;
            a4 = a_ok ? *(const float4*)An : make_float4(0.f, 0.f, 0.f, 0.f);
            b4 = *(const float4*)Bn;
        }
#pragma unroll
        for (int k = 0; k < BK; ++k) {
            union { float4 v; u64 u[2]; float f[4]; } al, ah, bl, bh;
            al.v = *(const float4*)&As[buf][k][ty * 4];
            ah.v = *(const float4*)&As[buf][k][64 + ty * 4];
            bl.v = *(const float4*)&Bs[buf][k][tx * 4];
            bh.v = *(const float4*)&Bs[buf][k][64 + tx * 4];
#pragma unroll
            for (int i = 0; i < 8; ++i) {
                float av = (i < 4) ? al.f[i] : ah.f[i - 4];
                u64 ad = dup2(av);
                acc[i][0] = fma2(ad, bl.u[0], acc[i][0]);
                acc[i][1] = fma2(ad, bl.u[1], acc[i][1]);
                acc[i][2] = fma2(ad, bh.u[0], acc[i][2]);
                acc[i][3] = fma2(ad, bh.u[1], acc[i][3]);
            }
        }
        buf ^= 1;
        if (kt + 1 < nk) {
            As[buf][lk + 0][lr] = a4.x; As[buf][lk + 1][lr] = a4.y;
            As[buf][lk + 2][lr] = a4.z; As[buf][lk + 3][lr] = a4.w;
            Bs[buf][lk + 0][lr] = b4.x; Bs[buf][lk + 1][lr] = b4.y;
            Bs[buf][lk + 2][lr] = b4.z; Bs[buf][lk + 3][lr] = b4.w;
            __syncthreads();
        }
    }

    // Epilogue
    float bvl[4], bvh[4];
    if (ADD_BIAS) {
        const float* bp = bias + (size_t)e * N + n0;
#pragma unroll
        for (int j = 0; j < 4; ++j) {
            bvl[j] = bp[tx * 4 + j];
            bvh[j] = bp[64 + tx * 4 + j];
        }
    }
#pragma unroll
    for (int i = 0; i < 8; ++i) {
        const int m = (i < 4) ? (ty * 4 + i) : (64 + ty * 4 + (i - 4));
        if (m < mrows) {
            float* crow = Cp + (size_t)(row0 + m) * N + n0;
            float2 v0 = *(float2*)&acc[i][0];
            float2 v1 = *(float2*)&acc[i][1];
            float2 v2 = *(float2*)&acc[i][2];
            float2 v3 = *(float2*)&acc[i][3];
            if (ADD_BIAS) {
                v0.x += bvl[0]; v0.y += bvl[1];
                v1.x += bvl[2]; v1.y += bvl[3];
                v2.x += bvh[0]; v2.y += bvh[1];
                v3.x += bvh[2]; v3.y += bvh[3];
            }
            *(float2*)&crow[tx * 4]          = v0;
            *(float2*)&crow[tx * 4 + 2]      = v1;
            *(float2*)&crow[64 + tx * 4]     = v2;
            *(float2*)&crow[64 + tx * 4 + 2] = v3;
        }
    }
}

extern "C" void kernel_launch(void* const* d_in, const int* in_sizes, int n_in,
                              void* d_out, int out_size) {
    const float* inp  = (const float*)d_in[0];   // [B, L, D_in]
    const int*   cnt  = (const int*)  d_in[1];   // [E]
    const float* wgt  = (const float*)d_in[2];   // [E, D_out, D_in]
    const float* bias = (const float*)d_in[3];   // [E, D_out]
    const float* comp = (const float*)d_in[4];   // [E, S, D_out]
    float* out = (float*)d_out;                  // [T, S] fp32

    const int E     = in_sizes[1];
    const int D_out = in_sizes[3] / E;
    const int D_in  = in_sizes[2] / in_sizes[3];          // (E*Do*Di)/(E*Do)
    const int T     = in_sizes[0] / D_in;
    const int S     = in_sizes[4] / in_sizes[3];          // (E*S*Do)/(E*Do)

    const int maxtiles = T / TM + E;  // upper bound on sum_e ceil(count_e/TM)

    setup_kernel<<<1, 1>>>(cnt, E);

    // GEMM1: y[t, o] = x[t, :] . W[e, o, :] + b[e, o]
    moe_gemm<true, 1><<<dim3(D_out / TN, maxtiles), NTHREADS>>>(
        inp, wgt, bias, nullptr, D_in, D_out);

    // GEMM2: out[t, s] = y[t, :] . C[e, s, :]
    moe_gemm<false, 2><<<dim3(S / TN, maxtiles), NTHREADS>>>(
        nullptr, comp, nullptr, out, D_out, S);
}

// round 4
// speedup vs baseline: 2.1818x; 2.1720x over previous
#include <cuda_runtime.h>
#include <cstdint>

// ---------------------------------------------------------------------------
// FMoELinearProj via legacy HMMA (mma.sync.m16n8k16.bf16) — plain sm_103 PTX
// target has no tcgen05, so we use warp-level MMA with register accumulators.
// fp32 emulated as bf16 2-term split: hi*hi + hi*lo + lo*hi (3 MMAs).
// CTA tile 128x128, K-tile 32 fp32, 8 warps (warp tile 32x64), double buffer.
// ---------------------------------------------------------------------------

#define BM 128
#define BN 128
#define BKF 32
#define NTH 256
#define SROW 80                       // smem bytes per row (64B data + 16B pad)
#define TILEB (128 * SROW)            // 10240 B per bf16 tile (128 rows)
#define OFF_ALO (TILEB)
#define OFF_BHI (2 * TILEB)
#define OFF_BLO (3 * TILEB)
#define STAGEB (4 * TILEB)            // 40960 B per stage
#define BIAS_OFF (2 * STAGEB)         // 81920
#define SMEM_TOTAL (BIAS_OFF + 512)

__device__ int   g_off[65];
__device__ int2  g_tiles[1024];
__device__ int   g_ntiles;
__device__ float g_y[8192ull * 4096ull];   // [T, D_out] fp32 intermediate

// ------------------------------- helpers -----------------------------------
__device__ __forceinline__ uint32_t smem_u32(const void* p) {
    uint32_t a;
    asm("{ .reg .u64 t; cvta.to.shared.u64 t, %1; cvt.u32.u64 %0, t; }"
        : "=r"(a) : "l"(p));
    return a;
}
__device__ __forceinline__ void ldsm4(uint32_t* r, uint32_t addr) {
    asm volatile("ldmatrix.sync.aligned.m8n8.x4.shared.b16 {%0,%1,%2,%3}, [%4];"
                 : "=r"(r[0]), "=r"(r[1]), "=r"(r[2]), "=r"(r[3]) : "r"(addr));
}
__device__ __forceinline__ void mma16816(float* c, const uint32_t* a,
                                         const uint32_t* b) {
    asm volatile(
        "mma.sync.aligned.m16n8k16.row.col.f32.bf16.bf16.f32 "
        "{%0,%1,%2,%3}, {%4,%5,%6,%7}, {%8,%9}, {%0,%1,%2,%3};"
        : "+f"(c[0]), "+f"(c[1]), "+f"(c[2]), "+f"(c[3])
        : "r"(a[0]), "r"(a[1]), "r"(a[2]), "r"(a[3]), "r"(b[0]), "r"(b[1]));
}
__device__ __forceinline__ void sts128(uint32_t a, uint32_t r0, uint32_t r1,
                                       uint32_t r2, uint32_t r3) {
    asm volatile("st.shared.v4.b32 [%0], {%1, %2, %3, %4};"
                 :: "r"(a), "r"(r0), "r"(r1), "r"(r2), "r"(r3) : "memory");
}
__device__ __forceinline__ float trunc16f(float a) {
    return __uint_as_float(__float_as_uint(a) & 0xFFFF0000u);
}
__device__ __forceinline__ uint32_t prmt_hi(float a, float b) {
    uint32_t d;
    asm("prmt.b32 %0, %1, %2, 0x7632;" : "=r"(d)
        : "r"(__float_as_uint(a)), "r"(__float_as_uint(b)));
    return d;
}
__device__ __forceinline__ uint32_t pack_lo(float e0, float e1) {
    uint32_t d;
    asm("cvt.rn.bf16x2.f32 %0, %1, %2;" : "=r"(d) : "f"(e1), "f"(e0));
    return d;
}
// Split 16 consecutive fp32 (4 float4) into bf16 hi/lo and store 2x16B each.
__device__ __forceinline__ void split_sts(uint32_t hib, uint32_t lob,
                                          const float4* v) {
#pragma unroll
    for (int j = 0; j < 2; ++j) {
        const float4 u0 = v[j * 2], u1 = v[j * 2 + 1];
        uint32_t h0 = prmt_hi(u0.x, u0.y);
        uint32_t h1 = prmt_hi(u0.z, u0.w);
        uint32_t h2 = prmt_hi(u1.x, u1.y);
        uint32_t h3 = prmt_hi(u1.z, u1.w);
        uint32_t l0 = pack_lo(u0.x - trunc16f(u0.x), u0.y - trunc16f(u0.y));
        uint32_t l1 = pack_lo(u0.z - trunc16f(u0.z), u0.w - trunc16f(u0.w));
        uint32_t l2 = pack_lo(u1.x - trunc16f(u1.x), u1.y - trunc16f(u1.y));
        uint32_t l3 = pack_lo(u1.z - trunc16f(u1.z), u1.w - trunc16f(u1.w));
        sts128(hib + j * 16, h0, h1, h2, h3);
        sts128(lob + j * 16, l0, l1, l2, l3);
    }
}

// ------------------------------ setup kernel -------------------------------
__global__ void setup_kernel(const int* __restrict__ counts, int E) {
    if (threadIdx.x == 0 && blockIdx.x == 0) {
        int off = 0, nt = 0;
        for (int e = 0; e < E; ++e) {
            g_off[e] = off;
            int c = counts[e];
            for (int m = 0; m < c; m += BM) { g_tiles[nt].x = e; g_tiles[nt].y = m; ++nt; }
            off += c;
        }
        g_off[E] = off;
        g_ntiles = nt;
    }
}

// ------------------------------ main GEMM kernel ---------------------------
// C[row, n] = sum_k A[row, k] * B[e, n, k] (+ bias). YMODE: 1 => C=g_y, 2 => A=g_y.
template <bool ADD_BIAS, int YMODE>
__global__ __launch_bounds__(NTH, 1)
void moe_hmma(const float* __restrict__ A, const float* __restrict__ Bm,
              const float* __restrict__ bias, float* __restrict__ C,
              int K, int N)
{
    const int tile = blockIdx.y;
    if (tile >= g_ntiles) return;
    const int e    = g_tiles[tile].x;
    const int m0   = g_tiles[tile].y;
    const int row0 = g_off[e] + m0;
    int mrows = g_off[e + 1] - g_off[e] - m0;
    if (mrows > BM) mrows = BM;
    const int n0 = blockIdx.x * BN;

    const float* Ap = (YMODE == 2) ? (const float*)g_y : A;
    float*       Cp = (YMODE == 1) ? g_y : C;

    extern __shared__ char smem[];
    const uint32_t sb = smem_u32(smem);
    const int tid = threadIdx.x, wid = tid >> 5, lane = tid & 31;
    const int warp_m = wid & 3, warp_n = wid >> 2;

    if (ADD_BIAS && tid < 32)
        ((float4*)(smem + BIAS_OFF))[tid] =
            *(const float4*)&bias[(size_t)e * N + n0 + tid * 4];

    // ---- global load mapping: 2 threads per row (halves of 32 fp32) ----
    const int lrow = tid >> 1;
    const int half = tid & 1;
    const bool aok = lrow < mrows;
    const float* Arow = Ap + ((size_t)(row0 + lrow)) * K + half * 16;
    const float* Brow = Bm + ((size_t)e * N + n0 + lrow) * K + half * 16;
    const uint32_t sA = lrow * SROW + half * 32;   // byte offset within tile
    const float4 z4 = make_float4(0.f, 0.f, 0.f, 0.f);

    float4 av[4], bv[4];
#pragma unroll
    for (int i = 0; i < 4; ++i) {
        av[i] = aok ? *(const float4*)(Arow + i * 4) : z4;
        bv[i] = *(const float4*)(Brow + i * 4);
    }
    {
        const uint32_t stg = sb;
        split_sts(stg + sA, stg + OFF_ALO + sA, av);
        split_sts(stg + OFF_BHI + sA, stg + OFF_BLO + sA, bv);
    }
    __syncthreads();

    float acc[2][8][4];
#pragma unroll
    for (int mi = 0; mi < 2; ++mi)
#pragma unroll
        for (int nj = 0; nj < 8; ++nj)
#pragma unroll
            for (int q = 0; q < 4; ++q) acc[mi][nj][q] = 0.f;

    // ldmatrix per-lane offsets (row-padded SROW layout, no swizzle needed)
    const uint32_t a_off = (uint32_t)(warp_m * 32 + (lane & 15)) * SROW +
                           ((lane >> 4) * 16);
    const uint32_t b_off = (uint32_t)(warp_n * 64 + (lane & 7) +
                                      ((lane >> 4) & 1) * 8) * SROW +
                           (((lane >> 3) & 1) * 16);

    const int nk = K >> 5;
    for (int kt = 0; kt < nk; ++kt) {
        const uint32_t stg = sb + (kt & 1) * STAGEB;
        // prefetch next k-tile into registers (overlaps MMA below)
        if (kt + 1 < nk) {
            const int ko = (kt + 1) * BKF;
#pragma unroll
            for (int i = 0; i < 4; ++i) {
                av[i] = aok ? *(const float4*)(Arow + ko + i * 4) : z4;
                bv[i] = *(const float4*)(Brow + ko + i * 4);
            }
        }
#pragma unroll
        for (int k16 = 0; k16 < 2; ++k16) {
            const uint32_t kb = k16 * 32;
            uint32_t ah[2][4], al[2][4], bb[4][4];
            ldsm4(ah[0], stg + a_off + kb);
            ldsm4(ah[1], stg + a_off + kb + 16 * SROW);
            ldsm4(al[0], stg + OFF_ALO + a_off + kb);
            ldsm4(al[1], stg + OFF_ALO + a_off + kb + 16 * SROW);
#pragma unroll
            for (int bj = 0; bj < 4; ++bj)
                ldsm4(bb[bj], stg + OFF_BHI + b_off + kb + bj * 16 * SROW);
            // term 1: hi * hi
#pragma unroll
            for (int mi = 0; mi < 2; ++mi)
#pragma unroll
                for (int nj = 0; nj < 8; ++nj)
                    mma16816(acc[mi][nj], ah[mi], &bb[nj >> 1][(nj & 1) * 2]);
            // term 2: lo * hi
#pragma unroll
            for (int mi = 0; mi < 2; ++mi)
#pragma unroll
                for (int nj = 0; nj < 8; ++nj)
                    mma16816(acc[mi][nj], al[mi], &bb[nj >> 1][(nj & 1) * 2]);
            // term 3: hi * lo (reload B frags from lo tile)
#pragma unroll
            for (int bj = 0; bj < 4; ++bj)
                ldsm4(bb[bj], stg + OFF_BLO + b_off + kb + bj * 16 * SROW);
#pragma unroll
            for (int mi = 0; mi < 2; ++mi)
#pragma unroll
                for (int nj = 0; nj < 8; ++nj)
                    mma16816(acc[mi][nj], ah[mi], &bb[nj >> 1][(nj & 1) * 2]);
        }
        __syncthreads();
        if (kt + 1 < nk) {
            const uint32_t nstg = sb + ((kt + 1) & 1) * STAGEB;
            split_sts(nstg + sA, nstg + OFF_ALO + sA, av);
            split_sts(nstg + OFF_BHI + sA, nstg + OFF_BLO + sA, bv);
            __syncthreads();
        }
    }

    // ------------------------------ epilogue --------------------------------
    const float* bs = (const float*)(smem + BIAS_OFF);
#pragma unroll
    for (int mi = 0; mi < 2; ++mi) {
        const int r = warp_m * 32 + mi * 16 + (lane >> 2);
#pragma unroll
        for (int nj = 0; nj < 8; ++nj) {
            const int c = warp_n * 64 + nj * 8 + (lane & 3) * 2;
            float2 v0 = make_float2(acc[mi][nj][0], acc[mi][nj][1]);
            float2 v1 = make_float2(acc[mi][nj][2], acc[mi][nj][3]);
            if (ADD_BIAS) {
                const float b0 = bs[c], b1 = bs[c + 1];
                v0.x += b0; v0.y += b1;
                v1.x += b0; v1.y += b1;
            }
            if (r < mrows)
                *(float2*)&Cp[(size_t)(row0 + r) * N + n0 + c] = v0;
            if (r + 8 < mrows)
                *(float2*)&Cp[(size_t)(row0 + r + 8) * N + n0 + c] = v1;
        }
    }
}

// ------------------------------- launch -------------------------------------
extern "C" void kernel_launch(void* const* d_in, const int* in_sizes, int n_in,
                              void* d_out, int out_size) {
    const float* inp  = (const float*)d_in[0];
    const int*   cnt  = (const int*)  d_in[1];
    const float* wgt  = (const float*)d_in[2];
    const float* bias = (const float*)d_in[3];
    const float* comp = (const float*)d_in[4];
    float* out = (float*)d_out;

    const int E     = in_sizes[1];
    const int D_out = in_sizes[3] / E;
    const int D_in  = in_sizes[2] / in_sizes[3];
    const int T     = in_sizes[0] / D_in;
    const int S     = in_sizes[4] / in_sizes[3];
    const int maxtiles = T / BM + E;

    cudaFuncSetAttribute(moe_hmma<true, 1>,
                         cudaFuncAttributeMaxDynamicSharedMemorySize, SMEM_TOTAL);
    cudaFuncSetAttribute(moe_hmma<false, 2>,
                         cudaFuncAttributeMaxDynamicSharedMemorySize, SMEM_TOTAL);

    setup_kernel<<<1, 1>>>(cnt, E);

    // GEMM1: y = x @ W^T + b
    moe_hmma<true, 1><<<dim3(D_out / BN, maxtiles), NTH, SMEM_TOTAL>>>(
        inp, wgt, bias, nullptr, D_in, D_out);
    // GEMM2: out = y @ C^T
    moe_hmma<false, 2><<<dim3(S / BN, maxtiles), NTH, SMEM_TOTAL>>>(
        nullptr, comp, nullptr, out, D_out, S);
}